// round 11
// baseline (speedup 1.0000x reference)
#include <cuda_runtime.h>
#include <math.h>

typedef unsigned long long ull;

// Problem constants
#define TT     2048
#define EE     768
#define HH     512          // H2
#define GATES  2048
#define KK     7
#define START_TAG 5
#define STOP_TAG  6
#define NEGV  -10000.0f

#define NCHK   256          // 8B h-chunks per direction (2 units each)

// ---------------- scratch (device globals; no runtime allocation) ----------
// gate pre-activations, gate-interleaved: g_preP[dir][t][unit] = {i,f,g,o}
__device__ float4 g_preP[2][TT][HH];        // 32 MB
__device__ float  g_hs[TT][2 * HH];         // 8 MB concat hidden states
__device__ float  g_feats[TT][KK];
// h broadcast: 8B value in a 16B slot (single-writer st.b64, self-validating).
// (TT+1) x 2 x 256 x 16B = 16.8 MB -> L2-resident.
__device__ ull g_h8[TT + 1][2][NCHK][2];

// ---------------------------------------------------------------------------
// packed f32x2 helpers (exact fp32 semantics, 2x FFMA throughput)
// ---------------------------------------------------------------------------
__device__ __forceinline__ void ffma2(ull& acc, ull a, ull b) {
    asm("fma.rn.f32x2 %0, %1, %2, %0;" : "+l"(acc) : "l"(a), "l"(b));
}
__device__ __forceinline__ void add2(ull& a, ull b) {
    asm("add.rn.f32x2 %0, %0, %1;" : "+l"(a) : "l"(b));
}
__device__ __forceinline__ ull pack2(float lo, float hi) {
    ull r;
    asm("mov.b64 %0, {%1, %2};" : "=l"(r) : "f"(lo), "f"(hi));
    return r;
}
__device__ __forceinline__ void unpack2(ull v, float& lo, float& hi) {
    asm("mov.b64 {%0, %1}, %2;" : "=f"(lo), "=f"(hi) : "l"(v));
}
__device__ __forceinline__ ull ldvol64(const ull* p) {
    ull v;
    asm volatile("ld.volatile.global.b64 %0, [%1];" : "=l"(v) : "l"(p));
    return v;
}
__device__ __forceinline__ float fsigm(float x) {
    return 1.f / (1.f + __expf(-x));
}
__device__ __forceinline__ float ftanh(float x) {
    return 2.f / (1.f + __expf(-2.f * x)) - 1.f;
}

// ---------------------------------------------------------------------------
// Kernel 0: NaN-prime g_h8. Every replay (captured in the graph).
// ---------------------------------------------------------------------------
__global__ void prime_kernel() {
    const float nv = __int_as_float(0x7fc00000);
    const ull nv2 = pack2(nv, nv);
    ull* p = &g_h8[0][0][0][0];
    const int n = (TT + 1) * 2 * NCHK * 2;
    for (int i = blockIdx.x * blockDim.x + threadIdx.x; i < n;
         i += gridDim.x * blockDim.x)
        p[i] = nv2;
}

__global__ void noop_kernel() {}   // spacer: ncu capture index 3 -> lstm_rec

// ---------------------------------------------------------------------------
// Kernel 1: pre = embeds(@dir) @ W_ih^T + (b_ih+b_hh), gate-interleaved out.
// (unchanged from R8/R10 — 128x128 tile, BK=8, double-buffered, f32x2)
// ---------------------------------------------------------------------------
#define GBM 128
#define GBN 128
#define GBK 8
__global__ __launch_bounds__(256) void gemm_pre(
        const float* __restrict__ embeds,
        const float* __restrict__ Wihf,
        const float* __restrict__ Wihb,
        const float* __restrict__ bihf, const float* __restrict__ bhhf,
        const float* __restrict__ bihb, const float* __restrict__ bhhb) {
    const int dir = blockIdx.z;
    const float* __restrict__ Wih = dir ? Wihb : Wihf;
    const float* __restrict__ bi  = dir ? bihb : bihf;
    const float* __restrict__ bh  = dir ? bhhb : bhhf;

    __shared__ __align__(16) float As[2][GBK][GBM];
    __shared__ __align__(16) float Bs[2][GBK][GBN];

    const int tid = threadIdx.x;
    const int m0 = blockIdx.y * GBM;
    const int n0 = blockIdx.x * GBN;

    const int lrow = tid >> 1;
    const int lcol = (tid & 1) * 4;
    const int arow = m0 + lrow;
    const int grow = dir ? (TT - 1 - arow) : arow;
    const float* ap = embeds + (size_t)grow * EE + lcol;
    const int nrow = n0 + lrow;
    const int prow = (nrow & 3) * HH + (nrow >> 2);
    const float* bp = Wih + (size_t)prow * EE + lcol;

    float4 av = *(const float4*)ap;
    float4 bv = *(const float4*)bp;
    As[0][lcol + 0][lrow] = av.x; As[0][lcol + 1][lrow] = av.y;
    As[0][lcol + 2][lrow] = av.z; As[0][lcol + 3][lrow] = av.w;
    Bs[0][lcol + 0][lrow] = bv.x; Bs[0][lcol + 1][lrow] = bv.y;
    Bs[0][lcol + 2][lrow] = bv.z; Bs[0][lcol + 3][lrow] = bv.w;
    __syncthreads();

    const int ty = tid >> 4, tx = tid & 15;
    const int mo = ty * 8, no = tx * 8;
    ull accp[8][4] = {};

    const int NTILES = EE / GBK;   // 96
    int buf = 0;
    for (int tIdx = 0; tIdx < NTILES; tIdx++) {
        if (tIdx + 1 < NTILES) {
            const int off = (tIdx + 1) * GBK;
            av = *(const float4*)(ap + off);
            bv = *(const float4*)(bp + off);
        }
#pragma unroll
        for (int k = 0; k < GBK; k++) {
            float a[8];
            *(float4*)&a[0] = *(const float4*)&As[buf][k][mo];
            *(float4*)&a[4] = *(const float4*)&As[buf][k][mo + 4];
            ull b2[4];
            *(ulonglong2*)&b2[0] = *(const ulonglong2*)&Bs[buf][k][no];
            *(ulonglong2*)&b2[2] = *(const ulonglong2*)&Bs[buf][k][no + 4];
#pragma unroll
            for (int i = 0; i < 8; i++) {
                const ull ad = pack2(a[i], a[i]);
#pragma unroll
                for (int jp = 0; jp < 4; jp++)
                    ffma2(accp[i][jp], ad, b2[jp]);
            }
        }
        if (tIdx + 1 < NTILES) {
            const int nb = buf ^ 1;
            As[nb][lcol + 0][lrow] = av.x; As[nb][lcol + 1][lrow] = av.y;
            As[nb][lcol + 2][lrow] = av.z; As[nb][lcol + 3][lrow] = av.w;
            Bs[nb][lcol + 0][lrow] = bv.x; Bs[nb][lcol + 1][lrow] = bv.y;
            Bs[nb][lcol + 2][lrow] = bv.z; Bs[nb][lcol + 3][lrow] = bv.w;
            __syncthreads();
            buf = nb;
        }
    }

    float bj[8];
#pragma unroll
    for (int j = 0; j < 8; j++) {
        const int n = n0 + no + j;
        const int pn = (n & 3) * HH + (n >> 2);
        bj[j] = bi[pn] + bh[pn];
    }
    const int u0 = (n0 + no) >> 2;
#pragma unroll
    for (int i = 0; i < 8; i++) {
        const int row = m0 + mo + i;
        float acc[8];
#pragma unroll
        for (int jp = 0; jp < 4; jp++)
            unpack2(accp[i][jp], acc[2 * jp], acc[2 * jp + 1]);
        float4 v0, v1;
        v0.x = acc[0] + bj[0]; v0.y = acc[1] + bj[1];
        v0.z = acc[2] + bj[2]; v0.w = acc[3] + bj[3];
        v1.x = acc[4] + bj[4]; v1.y = acc[5] + bj[5];
        v1.z = acc[6] + bj[6]; v1.w = acc[7] + bj[7];
        g_preP[dir][row][u0]     = v0;
        g_preP[dir][row][u0 + 1] = v1;
    }
}

// ---------------------------------------------------------------------------
// Kernel 2: WARP-AUTONOMOUS BiLSTM recurrence. grid (32,2), 256 threads.
// Each warp owns 2 hidden units (u0 = 2*gw, u0+1); its weights live in
// registers as f32x2 (128 regs/lane). Each lane polls 8 x 8B h-chunks and
// FMAs each chunk the moment it appears (progressive dot). Publish = ONE
// st.volatile.b64 by lane0 (atomic 8B, single-writer, self-validating).
// NO __syncthreads, NO SMEM — warps fully decoupled.
// ---------------------------------------------------------------------------
__global__ __launch_bounds__(256, 1) void lstm_rec(
        const float* __restrict__ h0,
        const float* __restrict__ c0,
        const float* __restrict__ Whhf,
        const float* __restrict__ Whhb) {
    const int dir  = blockIdx.y;
    const int tid  = threadIdx.x;
    const int w    = tid >> 5;
    const int lane = tid & 31;
    const int gw   = blockIdx.x * 8 + w;       // global warp id, 0..255
    const int u0   = gw * 2;                   // first owned unit
    const int par  = lane & 1;                 // 0 -> unit u0, 1 -> u0+1

    const float* __restrict__ Whh = dir ? Whhb : Whhf;

    // weights: Wp[u][g][j] = (W[u0+u][g][2c], W[u0+u][g][2c+1]), c = lane+32j
    ull Wp[2][4][8];
#pragma unroll
    for (int u = 0; u < 2; u++)
#pragma unroll
        for (int g = 0; g < 4; g++) {
            const ull* row = (const ull*)(Whh + (size_t)(g * HH + u0 + u) * HH);
#pragma unroll
            for (int j = 0; j < 8; j++)
                Wp[u][g][j] = row[lane + 32 * j];
        }

    float c = c0[dir * HH + u0 + par];
    float4 px = __ldg((const float4*)&g_preP[dir][0][u0 + par]);

    for (int t = 0; t < TT; t++) {
        // prefetch next pre-activation (gemm complete; plain load)
        float4 pn = make_float4(0.f, 0.f, 0.f, 0.f);
        if (t + 1 < TT) pn = __ldg((const float4*)&g_preP[dir][t + 1][u0 + par]);

        ull acc[2][4] = {};

#define DO_FMAS(J, H2)                                          \
        do {                                                    \
            ffma2(acc[0][0], (H2), Wp[0][0][J]);                \
            ffma2(acc[0][1], (H2), Wp[0][1][J]);                \
            ffma2(acc[0][2], (H2), Wp[0][2][J]);                \
            ffma2(acc[0][3], (H2), Wp[0][3][J]);                \
            ffma2(acc[1][0], (H2), Wp[1][0][J]);                \
            ffma2(acc[1][1], (H2), Wp[1][1][J]);                \
            ffma2(acc[1][2], (H2), Wp[1][2][J]);                \
            ffma2(acc[1][3], (H2), Wp[1][3][J]);                \
        } while (0)

        if (t == 0) {
            const ull* hp0 = (const ull*)(h0 + dir * HH);
#pragma unroll
            for (int j = 0; j < 8; j++) {
                const ull h2 = hp0[lane + 32 * j];
                DO_FMAS(j, h2);
            }
        } else {
            const ull* base = &g_h8[t][dir][0][0];
            unsigned pending = 0xFFu;
            while (__any_sync(0xffffffffu, pending)) {
#pragma unroll
                for (int j = 0; j < 8; j++) {
                    if (pending & (1u << j)) {
                        const ull h2 = ldvol64(base + (size_t)(lane + 32 * j) * 2);
                        float lo, hi; unpack2(h2, lo, hi);
                        if (lo == lo) {          // 8B store is atomic: valid
                            DO_FMAS(j, h2);
                            pending &= ~(1u << j);
                        }
                    }
                }
            }
        }
#undef DO_FMAS

        // fold lo+hi, pack (unit0, unit1) per gate, butterfly reduce
        ull vg[4];
#pragma unroll
        for (int g = 0; g < 4; g++) {
            float l0, h0_, l1, h1_;
            unpack2(acc[0][g], l0, h0_);
            unpack2(acc[1][g], l1, h1_);
            vg[g] = pack2(l0 + h0_, l1 + h1_);
        }
#pragma unroll
        for (int off = 16; off > 0; off >>= 1) {
#pragma unroll
            for (int g = 0; g < 4; g++)
                add2(vg[g], __shfl_xor_sync(0xffffffffu, vg[g], off));
        }

        // parity-select sums; gates computed in parallel (even=u0, odd=u0+1)
        float a[4];
#pragma unroll
        for (int g = 0; g < 4; g++) {
            float lo, hi; unpack2(vg[g], lo, hi);
            a[g] = par ? hi : lo;
        }
        const float ig = fsigm(px.x + a[0]);
        const float fg = fsigm(px.y + a[1]);
        const float og = fsigm(px.w + a[3]);
        c = fg * c + ig * ftanh(px.z + a[2]);
        const float hn = og * ftanh(c);

        // publish: lane0 packs (h_u0, h_u0+1) -> one atomic 8B store
        const float hn1 = __shfl_sync(0xffffffffu, hn, 1);
        if (lane == 0) {
            const ull hp = pack2(hn, hn1);
            ull* dst = &g_h8[t + 1][dir][gw][0];
            asm volatile("st.volatile.global.b64 [%0], %1;"
                         :: "l"(dst), "l"(hp) : "memory");
        }
        if (lane < 2) {                       // archival store AFTER publish
            const int trow = dir ? (TT - 1 - t) : t;
            g_hs[trow][dir * HH + u0 + lane] = hn;
        }
        px = pn;
    }
}

// ---------------------------------------------------------------------------
// Kernel 3: feats = [hs_f | hs_b] @ W_out^T + b_out   (grid = T, 256 threads)
// ---------------------------------------------------------------------------
__global__ void feats_kernel(const float* __restrict__ Wout,
                             const float* __restrict__ bout) {
    __shared__ __align__(16) float hsm[2 * HH];
    const int t = blockIdx.x;
    const int tid = threadIdx.x, w = tid >> 5, lane = tid & 31;
    ((float4*)hsm)[tid] = ((const float4*)&g_hs[t][0])[tid];
    __syncthreads();
    if (w < KK) {
        float acc = 0.f;
        const float* wr = Wout + w * 2 * HH;
        for (int k = lane; k < 2 * HH; k += 32) acc += hsm[k] * __ldg(wr + k);
#pragma unroll
        for (int off = 16; off; off >>= 1) acc += __shfl_down_sync(0xffffffffu, acc, off);
        if (lane == 0) g_feats[t][w] = acc + bout[w];
    }
}

// ---------------------------------------------------------------------------
// Kernel 4: Viterbi forward + backtrace. 1 block, 128 threads; feats in SMEM.
// ---------------------------------------------------------------------------
__global__ void viterbi_kernel(const float* __restrict__ trans,
                               float* __restrict__ out) {
    extern __shared__ __align__(16) float fsm[];   // [TT][KK] = 57344 B
    __shared__ signed char bp[TT][8];
    __shared__ signed char path_s[TT];
    const int tid = threadIdx.x;
    const int lane = tid & 31;

    {
        const float4* src = (const float4*)&g_feats[0][0];
        float4* dst = (float4*)fsm;
        const int n4 = TT * KK / 4;   // 3584
        for (int i = tid; i < n4; i += blockDim.x) dst[i] = src[i];
    }
    __syncthreads();

    if (tid < 32) {
        float tr[KK];
        if (lane < KK) {
#pragma unroll
            for (int j = 0; j < KK; j++) tr[j] = trans[lane * KK + j];
        }
        float fv = (lane == START_TAG) ? 0.f : NEGV;
        float fvv[KK];
#pragma unroll
        for (int j = 0; j < KK; j++) fvv[j] = __shfl_sync(0xffffffffu, fv, j);

        for (int t = 0; t < TT; t++) {
            if (lane < KK) {
                float v[KK];
#pragma unroll
                for (int j = 0; j < KK; j++) v[j] = fvv[j] + tr[j];
                float m01 = v[0]; int i01 = 0;
                if (v[1] > m01) { m01 = v[1]; i01 = 1; }
                float m23 = v[2]; int i23 = 2;
                if (v[3] > m23) { m23 = v[3]; i23 = 3; }
                float m45 = v[4]; int i45 = 4;
                if (v[5] > m45) { m45 = v[5]; i45 = 5; }
                float mA = m01; int iA = i01;
                if (m23 > mA) { mA = m23; iA = i23; }
                float mB = m45; int iB = i45;
                if (v[6] > mB) { mB = v[6]; iB = 6; }
                float m = mA; int im = iA;
                if (mB > m) { m = mB; im = iB; }
                bp[t][lane] = (signed char)im;
                fv = m + fsm[t * KK + lane];
            }
#pragma unroll
            for (int j = 0; j < KK; j++) fvv[j] = __shfl_sync(0xffffffffu, fv, j);
        }

        if (lane == 0) {
            float best = -1e30f; int bi = 0;
#pragma unroll
            for (int i = 0; i < KK; i++) {
                float v = fvv[i] + trans[STOP_TAG * KK + i];
                if (v > best) { best = v; bi = i; }
            }
            out[0] = best;
            int tag = bi;
            for (int t = TT - 1; t >= 0; t--) {
                path_s[t] = (signed char)tag;
                tag = bp[t][tag];
            }
        }
    }
    __syncthreads();
    for (int t = tid; t < TT; t += blockDim.x) out[1 + t] = (float)path_s[t];
}

// ---------------------------------------------------------------------------
extern "C" void kernel_launch(void* const* d_in, const int* in_sizes, int n_in,
                              void* d_out, int out_size) {
    const float* embeds = (const float*)d_in[0];
    const float* h0     = (const float*)d_in[1];
    const float* c0     = (const float*)d_in[2];
    const float* Wihf   = (const float*)d_in[3];
    const float* Whhf   = (const float*)d_in[4];
    const float* bihf   = (const float*)d_in[5];
    const float* bhhf   = (const float*)d_in[6];
    const float* Wihb   = (const float*)d_in[7];
    const float* Whhb   = (const float*)d_in[8];
    const float* bihb   = (const float*)d_in[9];
    const float* bhhb   = (const float*)d_in[10];
    const float* Wout   = (const float*)d_in[11];
    const float* bout   = (const float*)d_in[12];
    const float* trans  = (const float*)d_in[13];
    float* out = (float*)d_out;

    const int vit_smem = TT * KK * (int)sizeof(float);   // 57344
    cudaFuncSetAttribute(viterbi_kernel,
                         cudaFuncAttributeMaxDynamicSharedMemorySize, vit_smem);

    prime_kernel<<<1024, 256>>>();                       // index 0
    gemm_pre<<<dim3(GATES / GBN, TT / GBM, 2), 256>>>(   // index 1
        embeds, Wihf, Wihb, bihf, bhhf, bihb, bhhb);
    noop_kernel<<<1, 32>>>();                            // index 2 (spacer)
    lstm_rec<<<dim3(32, 2), 256>>>(h0, c0, Whhf, Whhb);  // index 3 -> ncu
    feats_kernel<<<TT, 256>>>(Wout, bout);               // index 4
    viterbi_kernel<<<1, 128, vit_smem>>>(trans, out);    // index 5
}

// round 12
// speedup vs baseline: 3.0967x; 3.0967x over previous
#include <cuda_runtime.h>
#include <math.h>

typedef unsigned long long ull;

// Problem constants
#define TT     2048
#define EE     768
#define HH     512          // H2
#define GATES  2048
#define KK     7
#define START_TAG 5
#define STOP_TAG  6
#define NEGV  -10000.0f

#define LSTM_CTAS 128       // 64 CTAs per direction (bids 0..127, wave-1 SMs)
#define CPD    64
#define UPB    8            // hidden units per CTA (1 per warp)
#define NCH    128          // 16B chunks per direction (HH/4)

#define FUSED_SMEM 196608   // 192KB/CTA -> exactly 1 CTA per SM (partition!)

// ---------------- scratch (device globals; no runtime allocation) ----------
// gate pre-activations, gate-interleaved: g_preP[dir][t][unit] = {i,f,g,o}
// NaN-primed each replay; lstm validates (gemm runs concurrently on own SMs).
__device__ float4 g_preP[2][TT][HH];        // 32 MB
__device__ float  g_hs[TT][2 * HH];         // 8 MB concat hidden states
__device__ float  g_feats[TT][KK];
// h broadcast: COMPACT (8.4 MB, L2-resident), NaN-primed, single-writer 16B.
__device__ float  g_hseq[TT + 1][2][HH];

// ---------------------------------------------------------------------------
// helpers
// ---------------------------------------------------------------------------
__device__ __forceinline__ void ffma2(ull& acc, ull a, ull b) {
    asm("fma.rn.f32x2 %0, %1, %2, %0;" : "+l"(acc) : "l"(a), "l"(b));
}
__device__ __forceinline__ ull pack2(float lo, float hi) {
    ull r;
    asm("mov.b64 %0, {%1, %2};" : "=l"(r) : "f"(lo), "f"(hi));
    return r;
}
__device__ __forceinline__ void unpack2(ull v, float& lo, float& hi) {
    asm("mov.b64 {%0, %1}, %2;" : "=f"(lo), "=f"(hi) : "l"(v));
}
__device__ __forceinline__ float sum2(ull v) {
    float lo, hi; unpack2(v, lo, hi); return lo + hi;
}
__device__ __forceinline__ float4 ldvol4(const float* p) {
    float4 v;
    asm volatile("ld.volatile.global.v4.f32 {%0,%1,%2,%3}, [%4];"
                 : "=f"(v.x), "=f"(v.y), "=f"(v.z), "=f"(v.w) : "l"(p));
    return v;
}
__device__ __forceinline__ float fsigm(float x) {
    return 1.f / (1.f + __expf(-x));
}
__device__ __forceinline__ float ftanh(float x) {
    return 2.f / (1.f + __expf(-2.f * x)) - 1.f;
}

// ---------------------------------------------------------------------------
// Kernel 0: NaN-prime g_preP (all) and g_hseq (all). Every replay.
// ---------------------------------------------------------------------------
__global__ void prime_kernel() {
    const float nv = __int_as_float(0x7fc00000);
    const float4 v = make_float4(nv, nv, nv, nv);
    const int idx = blockIdx.x * blockDim.x + threadIdx.x;
    const int stride = gridDim.x * blockDim.x;
    float4* pp = &g_preP[0][0][0];
    const int np = 2 * TT * HH;                    // 2M float4
    for (int i = idx; i < np; i += stride) pp[i] = v;
    float4* ph = (float4*)&g_hseq[0][0][0];
    const int nh = (TT + 1) * 2 * HH / 4;
    for (int i = idx; i < nh; i += stride) ph[i] = v;
}

// ---------------------------------------------------------------------------
// GEMM body: pre = embeds(@dir) @ W_ih^T + (b_ih+b_hh), gate-interleaved.
// 128x128 tile, BK=8, double-buffered, f32x2 accumulators. Tiles ordered
// t-ascending so early rows land first. Runs on the 20 SMs lstm doesn't own.
// ---------------------------------------------------------------------------
#define GBM 128
#define GBN 128
#define GBK 8
__device__ void gemm_body(
        char* smem_raw, int gi,
        const float* __restrict__ embeds,
        const float* __restrict__ Wihf,
        const float* __restrict__ Wihb,
        const float* __restrict__ bihf, const float* __restrict__ bhhf,
        const float* __restrict__ bihb, const float* __restrict__ bhhb) {
    const int tt  = gi >> 5;          // t-tile 0..15, ascending with bid
    const int rem = gi & 31;
    const int dir = rem >> 4;
    const int bx  = rem & 15;
    const float* __restrict__ Wih = dir ? Wihb : Wihf;
    const float* __restrict__ bi  = dir ? bihb : bihf;
    const float* __restrict__ bh  = dir ? bhhb : bhhf;

    float* As = (float*)smem_raw;           // [2][GBK][GBM] = 8KB
    float* Bs = (float*)smem_raw + 2048;    // [2][GBK][GBN] = 8KB
#define AS(b,k,r) As[((b) * GBK + (k)) * GBM + (r)]
#define BS(b,k,r) Bs[((b) * GBK + (k)) * GBN + (r)]

    const int tid = threadIdx.x;
    const int m0 = tt * GBM;
    const int n0 = bx * GBN;

    const int lrow = tid >> 1;
    const int lcol = (tid & 1) * 4;
    const int arow = m0 + lrow;
    const int grow = dir ? (TT - 1 - arow) : arow;
    const float* ap = embeds + (size_t)grow * EE + lcol;
    const int nrow = n0 + lrow;                       // interleaved column
    const int prow = (nrow & 3) * HH + (nrow >> 2);   // original W_ih row
    const float* bp = Wih + (size_t)prow * EE + lcol;

    float4 av = *(const float4*)ap;
    float4 bv = *(const float4*)bp;
    AS(0, lcol + 0, lrow) = av.x; AS(0, lcol + 1, lrow) = av.y;
    AS(0, lcol + 2, lrow) = av.z; AS(0, lcol + 3, lrow) = av.w;
    BS(0, lcol + 0, lrow) = bv.x; BS(0, lcol + 1, lrow) = bv.y;
    BS(0, lcol + 2, lrow) = bv.z; BS(0, lcol + 3, lrow) = bv.w;
    __syncthreads();

    const int ty = tid >> 4, tx = tid & 15;
    const int mo = ty * 8, no = tx * 8;
    ull accp[8][4] = {};

    const int NTILES = EE / GBK;   // 96
    int buf = 0;
    for (int tIdx = 0; tIdx < NTILES; tIdx++) {
        if (tIdx + 1 < NTILES) {
            const int off = (tIdx + 1) * GBK;
            av = *(const float4*)(ap + off);
            bv = *(const float4*)(bp + off);
        }
#pragma unroll
        for (int k = 0; k < GBK; k++) {
            float a[8];
            *(float4*)&a[0] = *(const float4*)&AS(buf, k, mo);
            *(float4*)&a[4] = *(const float4*)&AS(buf, k, mo + 4);
            ull b2[4];
            *(ulonglong2*)&b2[0] = *(const ulonglong2*)&BS(buf, k, no);
            *(ulonglong2*)&b2[2] = *(const ulonglong2*)&BS(buf, k, no + 4);
#pragma unroll
            for (int i = 0; i < 8; i++) {
                const ull ad = pack2(a[i], a[i]);
#pragma unroll
                for (int jp = 0; jp < 4; jp++)
                    ffma2(accp[i][jp], ad, b2[jp]);
            }
        }
        if (tIdx + 1 < NTILES) {
            const int nb = buf ^ 1;
            AS(nb, lcol + 0, lrow) = av.x; AS(nb, lcol + 1, lrow) = av.y;
            AS(nb, lcol + 2, lrow) = av.z; AS(nb, lcol + 3, lrow) = av.w;
            BS(nb, lcol + 0, lrow) = bv.x; BS(nb, lcol + 1, lrow) = bv.y;
            BS(nb, lcol + 2, lrow) = bv.z; BS(nb, lcol + 3, lrow) = bv.w;
            __syncthreads();
            buf = nb;
        }
    }

    float bj[8];
#pragma unroll
    for (int j = 0; j < 8; j++) {
        const int n = n0 + no + j;
        const int pn = (n & 3) * HH + (n >> 2);
        bj[j] = bi[pn] + bh[pn];
    }
    const int u0 = (n0 + no) >> 2;
#pragma unroll
    for (int i = 0; i < 8; i++) {
        const int row = m0 + mo + i;
        float acc[8];
#pragma unroll
        for (int jp = 0; jp < 4; jp++)
            unpack2(accp[i][jp], acc[2 * jp], acc[2 * jp + 1]);
        float4 v0, v1;
        v0.x = acc[0] + bj[0]; v0.y = acc[1] + bj[1];
        v0.z = acc[2] + bj[2]; v0.w = acc[3] + bj[3];
        v1.x = acc[4] + bj[4]; v1.y = acc[5] + bj[5];
        v1.z = acc[6] + bj[6]; v1.w = acc[7] + bj[7];
        g_preP[dir][row][u0]     = v0;   // single STG.128 per unit (atomic 16B)
        g_preP[dir][row][u0 + 1] = v1;
    }
#undef AS
#undef BS
}

// ---------------------------------------------------------------------------
// LSTM body: R10-proven protocol. 64 CTAs/dir, 8 warps (1 unit each).
// poll(128x16B, tight) -> SMEM -> BAR -> f32x2 dot -> reduce -> gates ->
// stage h8 -> BAR -> 2x STG.128 publish. px validated against NaN priming
// (gemm runs concurrently on its own SMs and stays ~9x ahead).
// ---------------------------------------------------------------------------
__device__ void lstm_body(
        char* smem_raw, int li,
        const float* __restrict__ h0,
        const float* __restrict__ c0,
        const float* __restrict__ Whhf,
        const float* __restrict__ Whhb) {
    float4* hsm4 = (float4*)smem_raw;                 // [2][NCH]
    float*  h8   = (float*)smem_raw + 4 * 2 * NCH;    // [UPB]
    const int dir  = li >> 6;
    const int sub  = li & 63;
    const int tid  = threadIdx.x;
    const int w    = tid >> 5;
    const int lane = tid & 31;
    const int gu   = sub * UPB + w;            // global hidden unit

    const float* __restrict__ Whh = dir ? Whhb : Whhf;

    // gate weights packed f32x2
    ull Wp[4][8];
#pragma unroll
    for (int g = 0; g < 4; g++) {
        const ulonglong2* row =
            (const ulonglong2*)(Whh + (size_t)(g * HH + gu) * HH);
#pragma unroll
        for (int i = 0; i < 4; i++) {
            ulonglong2 wp = row[lane + 32 * i];
            Wp[g][2 * i]     = wp.x;
            Wp[g][2 * i + 1] = wp.y;
        }
    }
    float c = c0[dir * HH + gu];

    // px(0): validate (gemm may not have produced row 0 yet)
    const float* p0 = (const float*)&g_preP[dir][0][gu];
    float4 px = ldvol4(p0);
    while (!(px.x == px.x)) px = ldvol4(p0);

    for (int t = 0; t < TT; t++) {
        const int buf = t & 1;
        // prefetch next pre-activation (validated at end of iteration)
        float4 pn = make_float4(0.f, 0.f, 0.f, 0.f);
        if (t + 1 < TT) pn = __ldg((const float4*)&g_preP[dir][t + 1][gu]);

        // acquire h(t) into hsm4[buf]  (R3/R10 protocol)
        if (tid < NCH) {
            float4 hv;
            if (t == 0) {
                hv = ((const float4*)h0)[dir * (HH / 4) + tid];
            } else if ((tid >> 1) == sub) {
                hv = ((const float4*)h8)[tid & 1];       // own chunk via SMEM
            } else {
                const float* pp = &g_hseq[t][dir][tid * 4];
                for (;;) {
                    hv = ldvol4(pp);
                    if (hv.x == hv.x) break;   // 16B chunk single-STG atomic
                }
            }
            hsm4[buf * NCH + tid] = hv;
        }
        __syncthreads();

        // dot: 4 gates x 512 via packed f32x2 FMA
        ull acc[4][2] = {};
        const ulonglong2* hp = (const ulonglong2*)&hsm4[buf * NCH];
#pragma unroll
        for (int i = 0; i < 4; i++) {
            const ulonglong2 h2 = hp[lane + 32 * i];
#pragma unroll
            for (int g = 0; g < 4; g++) {
                ffma2(acc[g][0], h2.x, Wp[g][2 * i]);
                ffma2(acc[g][1], h2.y, Wp[g][2 * i + 1]);
            }
        }
        float a0 = sum2(acc[0][0]) + sum2(acc[0][1]);
        float a1 = sum2(acc[1][0]) + sum2(acc[1][1]);
        float a2 = sum2(acc[2][0]) + sum2(acc[2][1]);
        float a3 = sum2(acc[3][0]) + sum2(acc[3][1]);

#pragma unroll
        for (int off = 16; off > 0; off >>= 1) {
            a0 += __shfl_xor_sync(0xffffffffu, a0, off);
            a1 += __shfl_xor_sync(0xffffffffu, a1, off);
            a2 += __shfl_xor_sync(0xffffffffu, a2, off);
            a3 += __shfl_xor_sync(0xffffffffu, a3, off);
        }

        const float ig = fsigm(px.x + a0);
        const float fg = fsigm(px.y + a1);
        const float og = fsigm(px.w + a3);
        c = fg * c + ig * ftanh(px.z + a2);
        const float hn = og * ftanh(c);

        if (lane == 0) h8[w] = hn;
        __syncthreads();                      // h8 complete; hsm reusable

        if (tid < 2) {                        // publish via 2x STG.128
            const float4 v = ((const float4*)h8)[tid];
            float* dst = &g_hseq[t + 1][dir][sub * UPB + tid * 4];
            asm volatile("st.volatile.global.v4.f32 [%0], {%1,%2,%3,%4};"
                         :: "l"(dst), "f"(v.x), "f"(v.y), "f"(v.z), "f"(v.w)
                         : "memory");
        }
        if (lane == 0) {                      // archival store AFTER publish
            const int trow = dir ? (TT - 1 - t) : t;
            g_hs[trow][dir * HH + gu] = hn;
        }

        // validate prefetched px(t+1); spin only if gemm lags (rare)
        if (t + 1 < TT && !(pn.x == pn.x)) {
            const float* pp = (const float*)&g_preP[dir][t + 1][gu];
            do { pn = ldvol4(pp); } while (!(pn.x == pn.x));
        }
        px = pn;
    }
}

// ---------------------------------------------------------------------------
// Fused kernel: grid 640 x 256, 192KB smem/CTA (=> exactly 1 CTA/SM).
// bids 0..127 (wave-1, distinct SMs): lstm. bids 128..639: gemm on the
// remaining 20 SMs (work-steal stays there — lstm SMs have no smem room).
// ---------------------------------------------------------------------------
__global__ void __launch_bounds__(256, 1) fused_kernel(
        const float* __restrict__ embeds,
        const float* __restrict__ h0,
        const float* __restrict__ c0,
        const float* __restrict__ Wihf, const float* __restrict__ Whhf,
        const float* __restrict__ bihf, const float* __restrict__ bhhf,
        const float* __restrict__ Wihb, const float* __restrict__ Whhb,
        const float* __restrict__ bihb, const float* __restrict__ bhhb) {
    extern __shared__ __align__(16) char smem_raw[];
    const int b = blockIdx.x;
    if (b < LSTM_CTAS)
        lstm_body(smem_raw, b, h0, c0, Whhf, Whhb);
    else
        gemm_body(smem_raw, b - LSTM_CTAS, embeds, Wihf, Wihb,
                  bihf, bhhf, bihb, bhhb);
}

// ---------------------------------------------------------------------------
// Kernel 3: feats = [hs_f | hs_b] @ W_out^T + b_out   (grid = T, 256 threads)
// ---------------------------------------------------------------------------
__global__ void feats_kernel(const float* __restrict__ Wout,
                             const float* __restrict__ bout) {
    __shared__ __align__(16) float hsm[2 * HH];
    const int t = blockIdx.x;
    const int tid = threadIdx.x, w = tid >> 5, lane = tid & 31;
    ((float4*)hsm)[tid] = ((const float4*)&g_hs[t][0])[tid];
    __syncthreads();
    if (w < KK) {
        float acc = 0.f;
        const float* wr = Wout + w * 2 * HH;
        for (int k = lane; k < 2 * HH; k += 32) acc += hsm[k] * __ldg(wr + k);
#pragma unroll
        for (int off = 16; off; off >>= 1) acc += __shfl_down_sync(0xffffffffu, acc, off);
        if (lane == 0) g_feats[t][w] = acc + bout[w];
    }
}

// ---------------------------------------------------------------------------
// Kernel 4: Viterbi forward + backtrace. 1 block, 128 threads; feats in SMEM.
// ---------------------------------------------------------------------------
__global__ void viterbi_kernel(const float* __restrict__ trans,
                               float* __restrict__ out) {
    extern __shared__ __align__(16) float fsm[];   // [TT][KK] = 57344 B
    __shared__ signed char bp[TT][8];
    __shared__ signed char path_s[TT];
    const int tid = threadIdx.x;
    const int lane = tid & 31;

    {
        const float4* src = (const float4*)&g_feats[0][0];
        float4* dst = (float4*)fsm;
        const int n4 = TT * KK / 4;   // 3584
        for (int i = tid; i < n4; i += blockDim.x) dst[i] = src[i];
    }
    __syncthreads();

    if (tid < 32) {
        float tr[KK];
        if (lane < KK) {
#pragma unroll
            for (int j = 0; j < KK; j++) tr[j] = trans[lane * KK + j];
        }
        float fv = (lane == START_TAG) ? 0.f : NEGV;
        float fvv[KK];
#pragma unroll
        for (int j = 0; j < KK; j++) fvv[j] = __shfl_sync(0xffffffffu, fv, j);

        for (int t = 0; t < TT; t++) {
            if (lane < KK) {
                float v[KK];
#pragma unroll
                for (int j = 0; j < KK; j++) v[j] = fvv[j] + tr[j];
                float m01 = v[0]; int i01 = 0;
                if (v[1] > m01) { m01 = v[1]; i01 = 1; }
                float m23 = v[2]; int i23 = 2;
                if (v[3] > m23) { m23 = v[3]; i23 = 3; }
                float m45 = v[4]; int i45 = 4;
                if (v[5] > m45) { m45 = v[5]; i45 = 5; }
                float mA = m01; int iA = i01;
                if (m23 > mA) { mA = m23; iA = i23; }
                float mB = m45; int iB = i45;
                if (v[6] > mB) { mB = v[6]; iB = 6; }
                float m = mA; int im = iA;
                if (mB > m) { m = mB; im = iB; }
                bp[t][lane] = (signed char)im;
                fv = m + fsm[t * KK + lane];
            }
#pragma unroll
            for (int j = 0; j < KK; j++) fvv[j] = __shfl_sync(0xffffffffu, fv, j);
        }

        if (lane == 0) {
            float best = -1e30f; int bi = 0;
#pragma unroll
            for (int i = 0; i < KK; i++) {
                float v = fvv[i] + trans[STOP_TAG * KK + i];
                if (v > best) { best = v; bi = i; }
            }
            out[0] = best;
            int tag = bi;
            for (int t = TT - 1; t >= 0; t--) {
                path_s[t] = (signed char)tag;
                tag = bp[t][tag];
            }
        }
    }
    __syncthreads();
    for (int t = tid; t < TT; t += blockDim.x) out[1 + t] = (float)path_s[t];
}

// ---------------------------------------------------------------------------
extern "C" void kernel_launch(void* const* d_in, const int* in_sizes, int n_in,
                              void* d_out, int out_size) {
    const float* embeds = (const float*)d_in[0];
    const float* h0     = (const float*)d_in[1];
    const float* c0     = (const float*)d_in[2];
    const float* Wihf   = (const float*)d_in[3];
    const float* Whhf   = (const float*)d_in[4];
    const float* bihf   = (const float*)d_in[5];
    const float* bhhf   = (const float*)d_in[6];
    const float* Wihb   = (const float*)d_in[7];
    const float* Whhb   = (const float*)d_in[8];
    const float* bihb   = (const float*)d_in[9];
    const float* bhhb   = (const float*)d_in[10];
    const float* Wout   = (const float*)d_in[11];
    const float* bout   = (const float*)d_in[12];
    const float* trans  = (const float*)d_in[13];
    float* out = (float*)d_out;

    const int vit_smem = TT * KK * (int)sizeof(float);   // 57344
    cudaFuncSetAttribute(viterbi_kernel,
                         cudaFuncAttributeMaxDynamicSharedMemorySize, vit_smem);
    cudaFuncSetAttribute(fused_kernel,
                         cudaFuncAttributeMaxDynamicSharedMemorySize, FUSED_SMEM);

    prime_kernel<<<2048, 256>>>();
    fused_kernel<<<LSTM_CTAS + 512, 256, FUSED_SMEM>>>(
        embeds, h0, c0, Wihf, Whhf, bihf, bhhf, Wihb, Whhb, bihb, bhhb);
    feats_kernel<<<TT, 256>>>(Wout, bout);
    viterbi_kernel<<<1, 128, vit_smem>>>(trans, out);
}